// round 10
// baseline (speedup 1.0000x reference)
#include <cuda_runtime.h>

// LWTA over groups of 4 consecutive fp32. Pure HBM-streaming kernel.
// R6: persistent single-wave grid (148 SMs x 8 CTAs, 256 thr) with a
// grid-stride loop over tiles. Eliminates multi-wave transition bubbles
// (~7 waves previously) and keeps the memory pipeline continuously fed.
// Per-iteration MLP=4 (the measured sweet spot from R2/R4).

#define NT  256      // threads per block
#define GPT 4        // float4 groups per thread per tile
#define NBLOCKS (148 * 8)   // one full wave at occ 8 (256 thr, 28 regs)

__global__ void __launch_bounds__(NT) lwta_kernel(const float4* __restrict__ in,
                                                  float4* __restrict__ out,
                                                  int n_tiles) {
    const int tile_sz = NT * GPT;   // 1024 groups per tile

    for (int t = blockIdx.x; t < n_tiles; t += gridDim.x) {
        int base = t * tile_sz + threadIdx.x;

        float4 v[GPT];
#pragma unroll
        for (int k = 0; k < GPT; k++) {
            v[k] = in[base + k * NT];
        }

#pragma unroll
        for (int k = 0; k < GPT; k++) {
            float4 x = v[k];
            // argmax, first-max-wins (strict >), matching jnp.argmax
            float m = x.x;
            int w = 0;
            if (x.y > m) { m = x.y; w = 1; }
            if (x.z > m) { m = x.z; w = 2; }
            if (x.w > m) { m = x.w; w = 3; }
            float4 r;
            r.x = (w == 0) ? x.x : 0.0f;
            r.y = (w == 1) ? x.y : 0.0f;
            r.z = (w == 2) ? x.z : 0.0f;
            r.w = (w == 3) ? x.w : 0.0f;
            v[k] = r;
        }

#pragma unroll
        for (int k = 0; k < GPT; k++) {
            out[base + k * NT] = v[k];
        }
    }
}

extern "C" void kernel_launch(void* const* d_in, const int* in_sizes, int n_in,
                              void* d_out, int out_size) {
    const float4* in = (const float4*)d_in[0];
    float4* out = (float4*)d_out;
    int n_elems = in_sizes[0];            // 4096*8192 = 33554432
    int n_groups = n_elems / 4;           // 8388608 float4 groups
    int n_tiles = n_groups / (NT * GPT);  // 8192, exact

    lwta_kernel<<<NBLOCKS, NT>>>(in, out, n_tiles);
}

// round 11
// speedup vs baseline: 1.1060x; 1.1060x over previous
#include <cuda_runtime.h>

// LWTA over groups of 4 consecutive fp32. Pure HBM-streaming kernel.
// R11: R4's best shape (512 thr, MLP=4, exact tiling, no guards) with
// L1-bypass cache ops (__ldcg/__stcg) — data is touched exactly once, so
// L1 line allocation on either stream is pure overhead. Isolates the
// cache-policy variable that R3 confounded with MLP=8.

#define GPT 4        // float4 groups per thread
#define NT  512      // threads per block

__global__ void __launch_bounds__(NT) lwta_kernel(const float4* __restrict__ in,
                                                  float4* __restrict__ out) {
    int base = blockIdx.x * (NT * GPT) + threadIdx.x;

    float4 v[GPT];

    // 4 independent coalesced loads, L2-only (no L1 allocation)
#pragma unroll
    for (int k = 0; k < GPT; k++) {
        v[k] = __ldcg(&in[base + k * NT]);
    }

#pragma unroll
    for (int k = 0; k < GPT; k++) {
        float4 x = v[k];
        // argmax, first-max-wins (strict >), matching jnp.argmax
        float m = x.x;
        int w = 0;
        if (x.y > m) { m = x.y; w = 1; }
        if (x.z > m) { m = x.z; w = 2; }
        if (x.w > m) { m = x.w; w = 3; }
        float4 r;
        r.x = (w == 0) ? x.x : 0.0f;
        r.y = (w == 1) ? x.y : 0.0f;
        r.z = (w == 2) ? x.z : 0.0f;
        r.w = (w == 3) ? x.w : 0.0f;
        v[k] = r;
    }

#pragma unroll
    for (int k = 0; k < GPT; k++) {
        __stcg(&out[base + k * NT], v[k]);
    }
}

extern "C" void kernel_launch(void* const* d_in, const int* in_sizes, int n_in,
                              void* d_out, int out_size) {
    const float4* in = (const float4*)d_in[0];
    float4* out = (float4*)d_out;
    int n_elems = in_sizes[0];                 // 4096*8192 = 33554432
    int n_groups = n_elems / 4;                // 8388608 float4 groups

    int groups_per_block = NT * GPT;           // 2048
    int blocks = n_groups / groups_per_block;  // 4096, exact
    lwta_kernel<<<blocks, NT>>>(in, out);
}